// round 1
// baseline (speedup 1.0000x reference)
#include <cuda_runtime.h>
#include <cstddef>

// Problem constants (dataset is fixed)
#define BATCH   32
#define TOK     256
#define DIM     1024
#define NPER    64
#define NNODES  2048          // BATCH*NPER
#define NEDGE   65536
#define OUTSZ   6176          // 32 energy + 2048*3 forces

// Scratch (static __device__ — no allocation allowed)
__device__ float g_hn[BATCH * DIM];          // LayerNorm'ed cls rows
__device__ float g_P[NNODES * 2 * DIM];      // [n][0:1024]=P1+bf1, [n][1024:2048]=P2

__device__ __forceinline__ float gelu_exact(float v) {
    return 0.5f * v * (1.0f + erff(v * 0.70710678118654752440f));
}

// ---------------------------------------------------------------------------
// init: energy[b] = be2[0]; forces = 0
// ---------------------------------------------------------------------------
__global__ void k_init(float* __restrict__ out, const float* __restrict__ be2) {
    int i = blockIdx.x * 256 + threadIdx.x;
    if (i < OUTSZ) out[i] = (i < BATCH) ? be2[0] : 0.0f;
}

// ---------------------------------------------------------------------------
// LayerNorm of cls rows: x[b,0,:] -> g_hn[b,:]
// ---------------------------------------------------------------------------
__global__ void k_ln(const float* __restrict__ x, const float* __restrict__ g,
                     const float* __restrict__ bb) {
    int b = blockIdx.x;
    int tid = threadIdx.x;                       // 256 threads, 1 float4 each
    const float4* row = (const float4*)(x + (size_t)b * TOK * DIM);
    float4 v = row[tid];
    float s  = v.x + v.y + v.z + v.w;
    float ss = v.x * v.x + v.y * v.y + v.z * v.z + v.w * v.w;
    __shared__ float r1[256], r2[256];
    r1[tid] = s; r2[tid] = ss;
    __syncthreads();
    for (int o = 128; o; o >>= 1) {
        if (tid < o) { r1[tid] += r1[tid + o]; r2[tid] += r2[tid + o]; }
        __syncthreads();
    }
    float mu  = r1[0] * (1.0f / DIM);
    float var = r2[0] * (1.0f / DIM) - mu * mu;
    float rs  = rsqrtf(var + 1e-5f);
    int k = tid * 4;
    float4 gg = ((const float4*)g)[tid];
    float4 bv = ((const float4*)bb)[tid];
    float* dst = g_hn + b * DIM + k;
    dst[0] = (v.x - mu) * rs * gg.x + bv.x;
    dst[1] = (v.y - mu) * rs * gg.y + bv.y;
    dst[2] = (v.z - mu) * rs * gg.z + bv.z;
    dst[3] = (v.w - mu) * rs * gg.w + bv.w;
}

// ---------------------------------------------------------------------------
// Energy head: for row b, cols j: acc = hn[b] . We1[:,j];
// v = gelu(acc + be1[j]); partial = v * We2[j]; block-reduce -> atomicAdd
// grid (8 col-tiles of 128, 32 rows), 128 threads
// ---------------------------------------------------------------------------
__global__ void __launch_bounds__(128) k_energy(
    const float* __restrict__ We1, const float* __restrict__ be1,
    const float* __restrict__ We2, float* __restrict__ out) {
    int b = blockIdx.y;
    int j = blockIdx.x * 128 + threadIdx.x;
    __shared__ float sh[DIM];
    for (int i = threadIdx.x; i < DIM; i += 128) sh[i] = g_hn[b * DIM + i];
    __syncthreads();
    float acc = 0.0f;
#pragma unroll 8
    for (int k = 0; k < DIM; k++) acc += sh[k] * We1[k * DIM + j];
    float v = gelu_exact(acc + be1[j]);
    float c = v * We2[j];
    __shared__ float red[128];
    red[threadIdx.x] = c;
    __syncthreads();
    for (int o = 64; o; o >>= 1) {
        if (threadIdx.x < o) red[threadIdx.x] += red[threadIdx.x + o];
        __syncthreads();
    }
    if (threadIdx.x == 0) atomicAdd(out + b, red[0]);
}

// ---------------------------------------------------------------------------
// SGEMM: P[n][j] = nodes[n] @ Wf1-half + (bf1 if j<1024)
//   nodes(n,k) = x[((n>>6)*256 + 1 + (n&63))*1024 + k]
//   cols j<1024 use Wf1 rows 0..1023; cols >=1024 use rows 1024..2047
// BM=128, BN=64, BK=16, 128 threads, TM=8, TN=8. grid (32, 16)
// ---------------------------------------------------------------------------
__global__ void __launch_bounds__(128) k_gemm(
    const float* __restrict__ x, const float* __restrict__ Wf1,
    const float* __restrict__ bf1) {
    __shared__ float As[16][128];
    __shared__ float Bs[16][64];
    const int tid = threadIdx.x;
    const int n0  = blockIdx.x * 64;          // 0..2047 output col base
    const int m0  = blockIdx.y * 128;         // row base
    const int half = (n0 >= DIM) ? 1 : 0;
    const int nb  = n0 - half * DIM;          // col within the Wf1 half
    const float* Bbase = Wf1 + (size_t)half * DIM * DIM;

    const int tm = tid >> 3;   // 0..15
    const int tn = tid & 7;    // 0..7

    float acc[8][8];
#pragma unroll
    for (int i = 0; i < 8; i++)
#pragma unroll
        for (int j = 0; j < 8; j++) acc[i][j] = 0.0f;

    for (int kt = 0; kt < DIM / 16; kt++) {
        int k0 = kt * 16;
        // A tile: 128 rows x 16 k, transposed into As[k][m]
#pragma unroll
        for (int i = 0; i < 4; i++) {
            int id  = tid + 128 * i;
            int row = id >> 2;
            int c4  = (id & 3) * 4;
            int n   = m0 + row;
            int nr  = ((n >> 6) << 8) + 1 + (n & 63);   // token row in x
            float4 v = *(const float4*)(x + (size_t)nr * DIM + k0 + c4);
            As[c4 + 0][row] = v.x;
            As[c4 + 1][row] = v.y;
            As[c4 + 2][row] = v.z;
            As[c4 + 3][row] = v.w;
        }
        // B tile: 16 k x 64 cols
#pragma unroll
        for (int i = 0; i < 2; i++) {
            int id = tid + 128 * i;
            int kr = id >> 4;
            int c4 = (id & 15) * 4;
            float4 v = *(const float4*)(Bbase + (size_t)(k0 + kr) * DIM + nb + c4);
            *(float4*)&Bs[kr][c4] = v;
        }
        __syncthreads();
#pragma unroll
        for (int kk = 0; kk < 16; kk++) {
            float a[8], bfr[8];
            *(float4*)&a[0]   = *(const float4*)&As[kk][tm * 8];
            *(float4*)&a[4]   = *(const float4*)&As[kk][tm * 8 + 4];
            *(float4*)&bfr[0] = *(const float4*)&Bs[kk][tn * 8];
            *(float4*)&bfr[4] = *(const float4*)&Bs[kk][tn * 8 + 4];
#pragma unroll
            for (int i = 0; i < 8; i++)
#pragma unroll
                for (int j = 0; j < 8; j++) acc[i][j] += a[i] * bfr[j];
        }
        __syncthreads();
    }
    // epilogue: fold bf1 into the first half, write P
    float bias[8];
#pragma unroll
    for (int j = 0; j < 8; j++) bias[j] = half ? 0.0f : bf1[nb + tn * 8 + j];
#pragma unroll
    for (int i = 0; i < 8; i++) {
        int gm = m0 + tm * 8 + i;
        float* dst = g_P + (size_t)gm * (2 * DIM) + n0 + tn * 8;
        float4 o0 = {acc[i][0] + bias[0], acc[i][1] + bias[1],
                     acc[i][2] + bias[2], acc[i][3] + bias[3]};
        float4 o1 = {acc[i][4] + bias[4], acc[i][5] + bias[5],
                     acc[i][6] + bias[6], acc[i][7] + bias[7]};
        *(float4*)dst       = o0;
        *(float4*)(dst + 4) = o1;
    }
}

// ---------------------------------------------------------------------------
// Edge phase: one warp per edge.
// hidden = P[i][0:1024] + P[j][1024:2048]  (bf1 already folded into P)
// fm = gelu(hidden) . Wf2 + bf2 ; forces[i] += fm * dvec/dist  (atomic)
// ---------------------------------------------------------------------------
__global__ void __launch_bounds__(256) k_edge(
    const int* __restrict__ ei, const float* __restrict__ dvec,
    const float* __restrict__ dist, const float* __restrict__ Wf2,
    const float* __restrict__ bf2, float* __restrict__ out) {
    int warp = threadIdx.x >> 5;
    int lane = threadIdx.x & 31;
    int e = blockIdx.x * 8 + warp;

    // Wf2 fragment is the same fixed 32 elements per lane for every edge
    float4 w2r[8];
    const float4* W2 = (const float4*)Wf2;
#pragma unroll
    for (int q = 0; q < 8; q++) w2r[q] = W2[lane + 32 * q];

    int i = ei[e];
    int j = ei[NEDGE + e];
    const float4* r1 = (const float4*)(g_P + (size_t)i * (2 * DIM));
    const float4* r2 = (const float4*)(g_P + (size_t)j * (2 * DIM) + DIM);

    float acc = 0.0f;
#pragma unroll
    for (int q = 0; q < 8; q++) {
        int t = lane + 32 * q;
        float4 a = r1[t];
        float4 c = r2[t];
        float4 w = w2r[q];
        acc += gelu_exact(a.x + c.x) * w.x;
        acc += gelu_exact(a.y + c.y) * w.y;
        acc += gelu_exact(a.z + c.z) * w.z;
        acc += gelu_exact(a.w + c.w) * w.w;
    }
#pragma unroll
    for (int o = 16; o; o >>= 1) acc += __shfl_xor_sync(0xffffffffu, acc, o);

    if (lane == 0) {
        float fm = acc + bf2[0];
        float s = fm / dist[e];
        float* f = out + BATCH + (size_t)i * 3;
        atomicAdd(f + 0, s * dvec[e * 3 + 0]);
        atomicAdd(f + 1, s * dvec[e * 3 + 1]);
        atomicAdd(f + 2, s * dvec[e * 3 + 2]);
    }
}

// ---------------------------------------------------------------------------
extern "C" void kernel_launch(void* const* d_in, const int* in_sizes, int n_in,
                              void* d_out, int out_size) {
    // metadata order: x, batch, edge_index, edge_distance_vec, edge_distance,
    // [natoms], ln_g, ln_b, We1, be1, We2, be2, Wf1, bf1, Wf2, bf2
    int o = (n_in == 16) ? 6 : 5;   // skip natoms scalar if present
    const float* x    = (const float*)d_in[0];
    const int*   ei   = (const int*)d_in[2];
    const float* dvec = (const float*)d_in[3];
    const float* dist = (const float*)d_in[4];
    const float* ln_g = (const float*)d_in[o + 0];
    const float* ln_b = (const float*)d_in[o + 1];
    const float* We1  = (const float*)d_in[o + 2];
    const float* be1  = (const float*)d_in[o + 3];
    const float* We2  = (const float*)d_in[o + 4];
    const float* be2  = (const float*)d_in[o + 5];
    const float* Wf1  = (const float*)d_in[o + 6];
    const float* bf1  = (const float*)d_in[o + 7];
    const float* Wf2  = (const float*)d_in[o + 8];
    const float* bf2  = (const float*)d_in[o + 9];
    float* out = (float*)d_out;

    k_init<<<(OUTSZ + 255) / 256, 256>>>(out, be2);
    k_ln<<<BATCH, 256>>>(x, ln_g, ln_b);
    k_gemm<<<dim3(32, 16), 128>>>(x, Wf1, bf1);
    k_energy<<<dim3(8, BATCH), 128>>>(We1, be1, We2, out);
    k_edge<<<NEDGE / 8, 256>>>(ei, dvec, dist, Wf2, bf2, out);
}

// round 3
// speedup vs baseline: 1.7842x; 1.7842x over previous
#include <cuda_runtime.h>
#include <cuda_bf16.h>
#include <cstdint>
#include <cstddef>

// Problem constants (dataset is fixed)
#define BATCH   32
#define TOK     256
#define DIM     1024
#define NPER    64
#define NNODES  2048          // BATCH*NPER
#define NEDGE   65536
#define OUTSZ   6176          // 32 energy + 2048*3 forces

// ---------------------------------------------------------------------------
// Scratch (static __device__ — no allocation allowed)
// ---------------------------------------------------------------------------
__device__ float g_hn[BATCH * DIM];                 // LayerNorm'ed cls rows
__device__ float g_P[NNODES * 2 * DIM];             // [n][0:1024]=P1+bf1, [n][1024:2048]=P2
__device__ __nv_bfloat16 g_Ahi[NNODES * DIM];       // nodes, bf16 hi
__device__ __nv_bfloat16 g_Alo[NNODES * DIM];       // nodes, bf16 lo
__device__ __nv_bfloat16 g_Bhi[2 * DIM * DIM];      // Wf1^T: [j'][k], bf16 hi
__device__ __nv_bfloat16 g_Blo[2 * DIM * DIM];      // Wf1^T: [j'][k], bf16 lo

__device__ __forceinline__ float gelu_exact(float v) {
    return 0.5f * v * (1.0f + erff(v * 0.70710678118654752440f));
}

__device__ __forceinline__ uint32_t smem_u32(const void* p) {
    uint32_t a;
    asm("{ .reg .u64 t; cvta.to.shared.u64 t, %1; cvt.u32.u64 %0, t; }" : "=r"(a) : "l"(p));
    return a;
}

#define CP_ASYNC16(dst, src) asm volatile("cp.async.cg.shared.global [%0], [%1], 16;" :: "r"(dst), "l"(src))
#define CP_COMMIT()          asm volatile("cp.async.commit_group;" ::: "memory")

__device__ __forceinline__ void ldm_x4(uint32_t* r, uint32_t addr) {
    asm volatile("ldmatrix.sync.aligned.m8n8.x4.shared.b16 {%0,%1,%2,%3}, [%4];"
        : "=r"(r[0]), "=r"(r[1]), "=r"(r[2]), "=r"(r[3]) : "r"(addr));
}

__device__ __forceinline__ void mma16816(float* d, const uint32_t* a, const uint32_t* b) {
    asm volatile("mma.sync.aligned.m16n8k16.row.col.f32.bf16.bf16.f32 "
        "{%0,%1,%2,%3}, {%4,%5,%6,%7}, {%8,%9}, {%0,%1,%2,%3};"
        : "+f"(d[0]), "+f"(d[1]), "+f"(d[2]), "+f"(d[3])
        : "r"(a[0]), "r"(a[1]), "r"(a[2]), "r"(a[3]), "r"(b[0]), "r"(b[1]));
}

// ---------------------------------------------------------------------------
// init: energy[b] = be2[0]; forces = 0
// ---------------------------------------------------------------------------
__global__ void k_init(float* __restrict__ out, const float* __restrict__ be2) {
    int i = blockIdx.x * 256 + threadIdx.x;
    if (i < OUTSZ) out[i] = (i < BATCH) ? be2[0] : 0.0f;
}

// ---------------------------------------------------------------------------
// LayerNorm of cls rows: x[b,0,:] -> g_hn[b,:]
// ---------------------------------------------------------------------------
__global__ void k_ln(const float* __restrict__ x, const float* __restrict__ g,
                     const float* __restrict__ bb) {
    int b = blockIdx.x;
    int tid = threadIdx.x;
    const float4* row = (const float4*)(x + (size_t)b * TOK * DIM);
    float4 v = row[tid];
    float s  = v.x + v.y + v.z + v.w;
    float ss = v.x * v.x + v.y * v.y + v.z * v.z + v.w * v.w;
    __shared__ float r1[256], r2[256];
    r1[tid] = s; r2[tid] = ss;
    __syncthreads();
    for (int o = 128; o; o >>= 1) {
        if (tid < o) { r1[tid] += r1[tid + o]; r2[tid] += r2[tid + o]; }
        __syncthreads();
    }
    float mu  = r1[0] * (1.0f / DIM);
    float var = r2[0] * (1.0f / DIM) - mu * mu;
    float rs  = rsqrtf(var + 1e-5f);
    int k = tid * 4;
    float4 gg = ((const float4*)g)[tid];
    float4 bv = ((const float4*)bb)[tid];
    float* dst = g_hn + b * DIM + k;
    dst[0] = (v.x - mu) * rs * gg.x + bv.x;
    dst[1] = (v.y - mu) * rs * gg.y + bv.y;
    dst[2] = (v.z - mu) * rs * gg.z + bv.z;
    dst[3] = (v.w - mu) * rs * gg.w + bv.w;
}

// ---------------------------------------------------------------------------
// Convert nodes -> bf16 hi/lo  (A matrix, K-major, [n][k])
// ---------------------------------------------------------------------------
__global__ void __launch_bounds__(256) k_cvt_a(const float* __restrict__ x) {
    int id = blockIdx.x * 256 + threadIdx.x;
    int base = id * 4;
    int n = base >> 10;
    int k = base & (DIM - 1);
    int nr = ((n >> 6) << 8) + 1 + (n & 63);       // token row in x
    float4 v = *(const float4*)(x + (size_t)nr * DIM + k);
    __nv_bfloat16 h0 = __float2bfloat16_rn(v.x);
    __nv_bfloat16 h1 = __float2bfloat16_rn(v.y);
    __nv_bfloat16 h2 = __float2bfloat16_rn(v.z);
    __nv_bfloat16 h3 = __float2bfloat16_rn(v.w);
    __nv_bfloat16 l0 = __float2bfloat16_rn(v.x - __bfloat162float(h0));
    __nv_bfloat16 l1 = __float2bfloat16_rn(v.y - __bfloat162float(h1));
    __nv_bfloat16 l2 = __float2bfloat16_rn(v.z - __bfloat162float(h2));
    __nv_bfloat16 l3 = __float2bfloat16_rn(v.w - __bfloat162float(h3));
    __nv_bfloat162* dh = (__nv_bfloat162*)(g_Ahi + (size_t)n * DIM + k);
    __nv_bfloat162* dl = (__nv_bfloat162*)(g_Alo + (size_t)n * DIM + k);
    dh[0] = __nv_bfloat162{h0, h1}; dh[1] = __nv_bfloat162{h2, h3};
    dl[0] = __nv_bfloat162{l0, l1}; dl[1] = __nv_bfloat162{l2, l3};
}

// ---------------------------------------------------------------------------
// Transpose Wf1 halves into K-major B, convert to bf16 hi/lo:
//   Bt[j'][k] = Wf1[half*1024 + k][j' mod 1024]
// ---------------------------------------------------------------------------
__global__ void k_cvt_w(const float* __restrict__ Wf1) {
    __shared__ float s[32][33];
    int jt = blockIdx.x, kt = blockIdx.y, half = blockIdx.z;
    int tx = threadIdx.x, ty = threadIdx.y;
    int krow = half * DIM + kt * 32 + ty;
    int j    = jt * 32 + tx;
    s[ty][tx] = Wf1[(size_t)krow * DIM + j];
    __syncthreads();
    int jp = half * DIM + jt * 32 + ty;            // output row (j')
    int k  = kt * 32 + tx;                         // output col (k)
    float v = s[tx][ty];
    __nv_bfloat16 h = __float2bfloat16_rn(v);
    __nv_bfloat16 l = __float2bfloat16_rn(v - __bfloat162float(h));
    g_Bhi[(size_t)jp * DIM + k] = h;
    g_Blo[(size_t)jp * DIM + k] = l;
}

// ---------------------------------------------------------------------------
// mma.sync bf16x3 GEMM:  P[m][n'] = sum_k A[m][k]*Bt[n'][k] (+bf1 if n'<1024)
// BM=BN=128, BK=32, 8 warps (2x4), warp tile 64x32, double-buffered cp.async.
// acc += Ahi*Bhi + Ahi*Blo + Alo*Bhi  (fp32 accumulate)
// ---------------------------------------------------------------------------
#define BK       32
#define TSTRIDE  40                         // bf16 elems per smem row (80B)
#define TILE_B   (128 * TSTRIDE * 2)        // 10240 bytes per tile
#define STAGE_B  (4 * TILE_B)               // Ahi,Alo,Bhi,Blo = 40960 bytes
#define GEMM_SMEM (2 * STAGE_B + 16)

__global__ void __launch_bounds__(256) k_gemm_mma(const float* __restrict__ bf1) {
    extern __shared__ __align__(16) char smem_raw[];
    const uint32_t sb = smem_u32(smem_raw);
    const int tid  = threadIdx.x;
    const int lane = tid & 31;
    const int warp = tid >> 5;
    const int n0 = blockIdx.x * 128;
    const int m0 = blockIdx.y * 128;
    const int wm0 = (warp >> 2) * 64;
    const int wn0 = (warp & 3) * 32;

    // load coords: per tile 512 16B-granules, 2 per thread
    const int r0 = (tid * 2) >> 2,      c0 = (tid * 2) & 3;
    const int r1 = (tid * 2 + 1) >> 2,  c1 = (tid * 2 + 1) & 3;

    float acc[4][4][4];
#pragma unroll
    for (int i = 0; i < 4; i++)
#pragma unroll
        for (int j = 0; j < 4; j++)
#pragma unroll
            for (int q = 0; q < 4; q++) acc[i][j][q] = 0.0f;

#define PREFETCH(stage, kb) do {                                                    \
    uint32_t st = sb + (stage) * STAGE_B;                                           \
    size_t eA0 = (size_t)(m0 + r0) * DIM + (kb) + c0 * 8;                           \
    size_t eA1 = (size_t)(m0 + r1) * DIM + (kb) + c1 * 8;                           \
    size_t eB0 = (size_t)(n0 + r0) * DIM + (kb) + c0 * 8;                           \
    size_t eB1 = (size_t)(n0 + r1) * DIM + (kb) + c1 * 8;                           \
    uint32_t o0 = r0 * (TSTRIDE * 2) + c0 * 16;                                     \
    uint32_t o1 = r1 * (TSTRIDE * 2) + c1 * 16;                                     \
    CP_ASYNC16(st + o0,              g_Ahi + eA0);                                  \
    CP_ASYNC16(st + o1,              g_Ahi + eA1);                                  \
    CP_ASYNC16(st + TILE_B + o0,     g_Alo + eA0);                                  \
    CP_ASYNC16(st + TILE_B + o1,     g_Alo + eA1);                                  \
    CP_ASYNC16(st + 2 * TILE_B + o0, g_Bhi + eB0);                                  \
    CP_ASYNC16(st + 2 * TILE_B + o1, g_Bhi + eB1);                                  \
    CP_ASYNC16(st + 3 * TILE_B + o0, g_Blo + eB0);                                  \
    CP_ASYNC16(st + 3 * TILE_B + o1, g_Blo + eB1);                                  \
} while (0)

    PREFETCH(0, 0);
    CP_COMMIT();

    for (int kt = 0; kt < DIM / BK; kt++) {
        if (kt + 1 < DIM / BK) {
            PREFETCH((kt + 1) & 1, (kt + 1) * BK);
            CP_COMMIT();
            asm volatile("cp.async.wait_group 1;" ::: "memory");
        } else {
            asm volatile("cp.async.wait_group 0;" ::: "memory");
        }
        __syncthreads();

        uint32_t st   = sb + (kt & 1) * STAGE_B;
        uint32_t sAhi = st;
        uint32_t sAlo = st + TILE_B;
        uint32_t sBhi = st + 2 * TILE_B;
        uint32_t sBlo = st + 3 * TILE_B;

#pragma unroll
        for (int ks = 0; ks < 2; ks++) {
            uint32_t k0b = ks * 32;                       // 16 elems * 2B
            uint32_t ahi[4][4], alo[4][4], bhi[2][4], blo[2][4];
#pragma unroll
            for (int mi = 0; mi < 4; mi++) {
                uint32_t row = wm0 + mi * 16 + (lane & 15);
                uint32_t off = row * (TSTRIDE * 2) + k0b + ((lane >> 4) << 4);
                ldm_x4(ahi[mi], sAhi + off);
                ldm_x4(alo[mi], sAlo + off);
            }
#pragma unroll
            for (int nj = 0; nj < 2; nj++) {
                uint32_t row = wn0 + nj * 16 + (lane & 7) + ((lane >> 4) << 3);
                uint32_t off = row * (TSTRIDE * 2) + k0b + (((lane >> 3) & 1) << 4);
                ldm_x4(bhi[nj], sBhi + off);
                ldm_x4(blo[nj], sBlo + off);
            }
#pragma unroll
            for (int mi = 0; mi < 4; mi++)
#pragma unroll
                for (int nt = 0; nt < 4; nt++) {
                    const uint32_t* bh = &bhi[nt >> 1][(nt & 1) * 2];
                    const uint32_t* bl = &blo[nt >> 1][(nt & 1) * 2];
                    mma16816(acc[mi][nt], ahi[mi], bh);
                    mma16816(acc[mi][nt], ahi[mi], bl);
                    mma16816(acc[mi][nt], alo[mi], bh);
                }
        }
        __syncthreads();
    }

    // epilogue: add bias on first half, store to g_P
#pragma unroll
    for (int mi = 0; mi < 4; mi++) {
        int gm = m0 + wm0 + mi * 16 + (lane >> 2);
#pragma unroll
        for (int nt = 0; nt < 4; nt++) {
            int gn = n0 + wn0 + nt * 8 + ((lane & 3) << 1);
            float b0 = 0.0f, b1 = 0.0f;
            if (gn < DIM) { b0 = bf1[gn]; b1 = bf1[gn + 1]; }
            float2 v0 = {acc[mi][nt][0] + b0, acc[mi][nt][1] + b1};
            float2 v1 = {acc[mi][nt][2] + b0, acc[mi][nt][3] + b1};
            *(float2*)(g_P + (size_t)gm * (2 * DIM) + gn)       = v0;
            *(float2*)(g_P + (size_t)(gm + 8) * (2 * DIM) + gn) = v1;
        }
    }
}

// ---------------------------------------------------------------------------
// Energy head: grid (32 col-tiles of 32, 32 rows), 128 threads.
// j = j0 + (tid&31), k-chunk kc = tid>>5 (256 k each)
// ---------------------------------------------------------------------------
__global__ void __launch_bounds__(128) k_energy(
    const float* __restrict__ We1, const float* __restrict__ be1,
    const float* __restrict__ We2, float* __restrict__ out) {
    int b  = blockIdx.y;
    int j0 = blockIdx.x * 32;
    int jl = threadIdx.x & 31;
    int kc = threadIdx.x >> 5;
    __shared__ float sh[DIM];
    for (int i = threadIdx.x; i < DIM; i += 128) sh[i] = g_hn[b * DIM + i];
    __syncthreads();
    int j = j0 + jl;
    float acc = 0.0f;
    const float* W = We1 + (size_t)(kc * 256) * DIM + j;
    const float* H = sh + kc * 256;
#pragma unroll 8
    for (int k = 0; k < 256; k++) acc += H[k] * W[(size_t)k * DIM];
    __shared__ float red[128];
    red[threadIdx.x] = acc;
    __syncthreads();
    if (threadIdx.x < 32) {
        float s = red[jl] + red[jl + 32] + red[jl + 64] + red[jl + 96];
        float v = gelu_exact(s + be1[j]) * We2[j];
#pragma unroll
        for (int o = 16; o; o >>= 1) v += __shfl_xor_sync(0xffffffffu, v, o);
        if (jl == 0) atomicAdd(out + b, v);
    }
}

// ---------------------------------------------------------------------------
// Edge phase: one warp per edge.
// ---------------------------------------------------------------------------
__global__ void __launch_bounds__(256) k_edge(
    const int* __restrict__ ei, const float* __restrict__ dvec,
    const float* __restrict__ dist, const float* __restrict__ Wf2,
    const float* __restrict__ bf2, float* __restrict__ out) {
    int warp = threadIdx.x >> 5;
    int lane = threadIdx.x & 31;
    int e = blockIdx.x * 8 + warp;

    float4 w2r[8];
    const float4* W2 = (const float4*)Wf2;
#pragma unroll
    for (int q = 0; q < 8; q++) w2r[q] = W2[lane + 32 * q];

    int i = ei[e];
    int j = ei[NEDGE + e];
    const float4* r1 = (const float4*)(g_P + (size_t)i * (2 * DIM));
    const float4* r2 = (const float4*)(g_P + (size_t)j * (2 * DIM) + DIM);

    float acc = 0.0f;
#pragma unroll
    for (int q = 0; q < 8; q++) {
        int t = lane + 32 * q;
        float4 a = r1[t];
        float4 c = r2[t];
        float4 w = w2r[q];
        acc += gelu_exact(a.x + c.x) * w.x;
        acc += gelu_exact(a.y + c.y) * w.y;
        acc += gelu_exact(a.z + c.z) * w.z;
        acc += gelu_exact(a.w + c.w) * w.w;
    }
#pragma unroll
    for (int o = 16; o; o >>= 1) acc += __shfl_xor_sync(0xffffffffu, acc, o);

    if (lane == 0) {
        float fm = acc + bf2[0];
        float s = fm / dist[e];
        float* f = out + BATCH + (size_t)i * 3;
        atomicAdd(f + 0, s * dvec[e * 3 + 0]);
        atomicAdd(f + 1, s * dvec[e * 3 + 1]);
        atomicAdd(f + 2, s * dvec[e * 3 + 2]);
    }
}

// ---------------------------------------------------------------------------
extern "C" void kernel_launch(void* const* d_in, const int* in_sizes, int n_in,
                              void* d_out, int out_size) {
    int o = (n_in == 16) ? 6 : 5;
    const float* x    = (const float*)d_in[0];
    const int*   ei   = (const int*)d_in[2];
    const float* dvec = (const float*)d_in[3];
    const float* dist = (const float*)d_in[4];
    const float* ln_g = (const float*)d_in[o + 0];
    const float* ln_b = (const float*)d_in[o + 1];
    const float* We1  = (const float*)d_in[o + 2];
    const float* be1  = (const float*)d_in[o + 3];
    const float* We2  = (const float*)d_in[o + 4];
    const float* be2  = (const float*)d_in[o + 5];
    const float* Wf1  = (const float*)d_in[o + 6];
    const float* bf1  = (const float*)d_in[o + 7];
    const float* Wf2  = (const float*)d_in[o + 8];
    const float* bf2  = (const float*)d_in[o + 9];
    float* out = (float*)d_out;

    static int smem_set = 0;
    if (!smem_set) {
        cudaFuncSetAttribute(k_gemm_mma, cudaFuncAttributeMaxDynamicSharedMemorySize,
                             GEMM_SMEM);
        smem_set = 1;
    }

    k_init<<<(OUTSZ + 255) / 256, 256>>>(out, be2);
    k_ln<<<BATCH, 256>>>(x, ln_g, ln_b);
    k_cvt_a<<<NNODES * DIM / 4 / 256, 256>>>(x);
    k_cvt_w<<<dim3(32, 32, 2), dim3(32, 32)>>>(Wf1);
    k_gemm_mma<<<dim3(16, 16), 256, GEMM_SMEM>>>(bf1);
    k_energy<<<dim3(32, BATCH), 128>>>(We1, be1, We2, out);
    k_edge<<<NEDGE / 8, 256>>>(ei, dvec, dist, Wf2, bf2, out);
}